// round 12
// baseline (speedup 1.0000x reference)
#include <cuda_runtime.h>

// B=16384, N=100000, D=128, F1=64, F2=32
// Algebraic collapse: the deep path is affine in the gathered embedding row, so
//   y[b] = dot(emb[x[b]], v) + Wo[F2 + x[b]] + c
//   u = W2^T @ Wo[0:32] (64),  v = W1^T @ u (128),  c = b1.u + b2.wo + bo
// prep kernel computes v/c once and fires ProgrammaticLaunchCompletion right
// after its writes; main kernel (PDL) issues all prep-independent gathers
// (4 rows/warp, MLP=4, fully coalesced 512B row loads), then
// GridDependencySynchronize before reading v/c. 512 blocks x 256 threads.
// Benches at the harness floor (10.72us, reproduced 3x).

__device__ float g_v[128];
__device__ float g_c;

__global__ void wdl_prep_kernel(const float* __restrict__ W1,
                                const float* __restrict__ b1,
                                const float* __restrict__ W2,
                                const float* __restrict__ b2,
                                const float* __restrict__ Wo,
                                const float* __restrict__ bo) {
    __shared__ float u[64];
    int t = threadIdx.x;  // 128 threads
    if (t < 64) {
        float s = 0.f;
        #pragma unroll
        for (int k = 0; k < 32; k++) s += W2[k * 64 + t] * Wo[k];
        u[t] = s;
    }
    __syncthreads();
    {
        float s = 0.f;
        #pragma unroll
        for (int j = 0; j < 64; j++) s += W1[j * 128 + t] * u[j];
        g_v[t] = s;
    }
    if (t < 32) {
        float cc = u[t] * b1[t] + u[t + 32] * b1[t + 32] + b2[t] * Wo[t];
        #pragma unroll
        for (int off = 16; off; off >>= 1)
            cc += __shfl_xor_sync(0xffffffff, cc, off);
        if (t == 0) g_c = cc + bo[0];
    }
    // Release the dependent (PDL) grid as soon as our writes are done,
    // instead of waiting for full kernel retirement.
    __syncthreads();
    cudaTriggerProgrammaticLaunchCompletion();
}

#define THREADS 256
#define ROWS_PER_WARP 4
#define ROWS_PER_BLOCK (ROWS_PER_WARP * (THREADS / 32))  // 32

__global__ void __launch_bounds__(THREADS) wdl_main_kernel(
    const int*   __restrict__ x,
    const float* __restrict__ emb,
    const float* __restrict__ Wo,
    float* __restrict__ out) {
    int t    = threadIdx.x;
    int lane = t & 31;
    int warp = t >> 5;
    int base = blockIdx.x * ROWS_PER_BLOCK + warp * ROWS_PER_WARP;

    // ---- prep-independent work: issue every gather before the PDL sync ----
    int idxl = 0;
    if (lane < ROWS_PER_WARP) idxl = x[base + lane];
    int i0 = __shfl_sync(0xffffffff, idxl, 0);
    int i1 = __shfl_sync(0xffffffff, idxl, 1);
    int i2 = __shfl_sync(0xffffffff, idxl, 2);
    int i3 = __shfl_sync(0xffffffff, idxl, 3);

    const float4* E = reinterpret_cast<const float4*>(emb);
    float4 a0 = E[(long)i0 * 32 + lane];
    float4 a1 = E[(long)i1 * 32 + lane];
    float4 a2 = E[(long)i2 * 32 + lane];
    float4 a3 = E[(long)i3 * 32 + lane];
    float  wol = 0.f;
    if (lane < ROWS_PER_WARP) wol = Wo[32 + idxl];

    // ---- wait for prep kernel's writes (PDL dependency) ----
    cudaGridDependencySynchronize();

    float4 b = reinterpret_cast<const float4*>(g_v)[lane];
    float  c = g_c;

    float s0 = a0.x * b.x + a0.y * b.y + a0.z * b.z + a0.w * b.w;
    float s1 = a1.x * b.x + a1.y * b.y + a1.z * b.z + a1.w * b.w;
    float s2 = a2.x * b.x + a2.y * b.y + a2.z * b.z + a2.w * b.w;
    float s3 = a3.x * b.x + a3.y * b.y + a3.z * b.z + a3.w * b.w;

    #pragma unroll
    for (int off = 16; off; off >>= 1) {
        s0 += __shfl_xor_sync(0xffffffff, s0, off);
        s1 += __shfl_xor_sync(0xffffffff, s1, off);
        s2 += __shfl_xor_sync(0xffffffff, s2, off);
        s3 += __shfl_xor_sync(0xffffffff, s3, off);
    }

    if (lane < ROWS_PER_WARP) {
        float sv = (lane < 2) ? ((lane == 0) ? s0 : s1)
                              : ((lane == 2) ? s2 : s3);
        out[base + lane] = sv + wol + c;
    }
}

extern "C" void kernel_launch(void* const* d_in, const int* in_sizes, int n_in,
                              void* d_out, int out_size) {
    const int*   x   = (const int*)d_in[0];
    const float* emb = (const float*)d_in[1];
    const float* W1  = (const float*)d_in[2];
    const float* b1  = (const float*)d_in[3];
    const float* W2  = (const float*)d_in[4];
    const float* b2  = (const float*)d_in[5];
    const float* Wo  = (const float*)d_in[6];
    const float* bo  = (const float*)d_in[7];
    float* out = (float*)d_out;

    const int B = in_sizes[0];  // 16384

    wdl_prep_kernel<<<1, 128>>>(W1, b1, W2, b2, Wo, bo);

    cudaLaunchConfig_t cfg = {};
    cfg.gridDim  = dim3(B / ROWS_PER_BLOCK);  // 512
    cfg.blockDim = dim3(THREADS);
    cfg.dynamicSmemBytes = 0;
    cfg.stream = 0;
    cudaLaunchAttribute attrs[1];
    attrs[0].id = cudaLaunchAttributeProgrammaticStreamSerialization;
    attrs[0].val.programmaticStreamSerializationAllowed = 1;
    cfg.attrs = attrs;
    cfg.numAttrs = 1;
    cudaLaunchKernelEx(&cfg, wdl_main_kernel, x, emb, Wo, (float*)d_out);
}

// round 13
// speedup vs baseline: 1.0238x; 1.0238x over previous
#include <cuda_runtime.h>

// B=16384, N=100000, D=128, F1=64, F2=32
// Algebraic collapse: the deep path is affine in the gathered embedding row, so
//   y[b] = dot(emb[x[b]], v) + Wo[F2 + x[b]] + c
//   u = W2^T @ Wo[0:32] (64),  v = W1^T @ u (128),  c = b1.u + b2.wo + bo
// prep kernel computes v/c once and fires ProgrammaticLaunchCompletion right
// after its writes; main kernel (PDL) issues all prep-independent gathers
// (4 rows/warp, MLP=4, fully coalesced 512B row loads), then
// GridDependencySynchronize before reading v/c. 512 blocks x 256 threads.
// Benches at the harness floor (10.72us x3; identical binary re-run spread
// 10.72-11.01us => remaining variation is measurement noise).

__device__ float g_v[128];
__device__ float g_c;

__global__ void wdl_prep_kernel(const float* __restrict__ W1,
                                const float* __restrict__ b1,
                                const float* __restrict__ W2,
                                const float* __restrict__ b2,
                                const float* __restrict__ Wo,
                                const float* __restrict__ bo) {
    __shared__ float u[64];
    int t = threadIdx.x;  // 128 threads
    if (t < 64) {
        float s = 0.f;
        #pragma unroll
        for (int k = 0; k < 32; k++) s += W2[k * 64 + t] * Wo[k];
        u[t] = s;
    }
    __syncthreads();
    {
        float s = 0.f;
        #pragma unroll
        for (int j = 0; j < 64; j++) s += W1[j * 128 + t] * u[j];
        g_v[t] = s;
    }
    if (t < 32) {
        float cc = u[t] * b1[t] + u[t + 32] * b1[t + 32] + b2[t] * Wo[t];
        #pragma unroll
        for (int off = 16; off; off >>= 1)
            cc += __shfl_xor_sync(0xffffffff, cc, off);
        if (t == 0) g_c = cc + bo[0];
    }
    // Release the dependent (PDL) grid as soon as our writes are done,
    // instead of waiting for full kernel retirement.
    __syncthreads();
    cudaTriggerProgrammaticLaunchCompletion();
}

#define THREADS 256
#define ROWS_PER_WARP 4
#define ROWS_PER_BLOCK (ROWS_PER_WARP * (THREADS / 32))  // 32

__global__ void __launch_bounds__(THREADS) wdl_main_kernel(
    const int*   __restrict__ x,
    const float* __restrict__ emb,
    const float* __restrict__ Wo,
    float* __restrict__ out) {
    int t    = threadIdx.x;
    int lane = t & 31;
    int warp = t >> 5;
    int base = blockIdx.x * ROWS_PER_BLOCK + warp * ROWS_PER_WARP;

    // ---- prep-independent work: issue every gather before the PDL sync ----
    int idxl = 0;
    if (lane < ROWS_PER_WARP) idxl = x[base + lane];
    int i0 = __shfl_sync(0xffffffff, idxl, 0);
    int i1 = __shfl_sync(0xffffffff, idxl, 1);
    int i2 = __shfl_sync(0xffffffff, idxl, 2);
    int i3 = __shfl_sync(0xffffffff, idxl, 3);

    const float4* E = reinterpret_cast<const float4*>(emb);
    float4 a0 = E[(long)i0 * 32 + lane];
    float4 a1 = E[(long)i1 * 32 + lane];
    float4 a2 = E[(long)i2 * 32 + lane];
    float4 a3 = E[(long)i3 * 32 + lane];
    float  wol = 0.f;
    if (lane < ROWS_PER_WARP) wol = Wo[32 + idxl];

    // ---- wait for prep kernel's writes (PDL dependency) ----
    cudaGridDependencySynchronize();

    float4 b = reinterpret_cast<const float4*>(g_v)[lane];
    float  c = g_c;

    float s0 = a0.x * b.x + a0.y * b.y + a0.z * b.z + a0.w * b.w;
    float s1 = a1.x * b.x + a1.y * b.y + a1.z * b.z + a1.w * b.w;
    float s2 = a2.x * b.x + a2.y * b.y + a2.z * b.z + a2.w * b.w;
    float s3 = a3.x * b.x + a3.y * b.y + a3.z * b.z + a3.w * b.w;

    #pragma unroll
    for (int off = 16; off; off >>= 1) {
        s0 += __shfl_xor_sync(0xffffffff, s0, off);
        s1 += __shfl_xor_sync(0xffffffff, s1, off);
        s2 += __shfl_xor_sync(0xffffffff, s2, off);
        s3 += __shfl_xor_sync(0xffffffff, s3, off);
    }

    if (lane < ROWS_PER_WARP) {
        float sv = (lane < 2) ? ((lane == 0) ? s0 : s1)
                              : ((lane == 2) ? s2 : s3);
        out[base + lane] = sv + wol + c;
    }
}

extern "C" void kernel_launch(void* const* d_in, const int* in_sizes, int n_in,
                              void* d_out, int out_size) {
    const int*   x   = (const int*)d_in[0];
    const float* emb = (const float*)d_in[1];
    const float* W1  = (const float*)d_in[2];
    const float* b1  = (const float*)d_in[3];
    const float* W2  = (const float*)d_in[4];
    const float* b2  = (const float*)d_in[5];
    const float* Wo  = (const float*)d_in[6];
    const float* bo  = (const float*)d_in[7];
    float* out = (float*)d_out;

    const int B = in_sizes[0];  // 16384

    wdl_prep_kernel<<<1, 128>>>(W1, b1, W2, b2, Wo, bo);

    cudaLaunchConfig_t cfg = {};
    cfg.gridDim  = dim3(B / ROWS_PER_BLOCK);  // 512
    cfg.blockDim = dim3(THREADS);
    cfg.dynamicSmemBytes = 0;
    cfg.stream = 0;
    cudaLaunchAttribute attrs[1];
    attrs[0].id = cudaLaunchAttributeProgrammaticStreamSerialization;
    attrs[0].val.programmaticStreamSerializationAllowed = 1;
    cfg.attrs = attrs;
    cfg.numAttrs = 1;
    cudaLaunchKernelEx(&cfg, wdl_main_kernel, x, emb, Wo, (float*)d_out);
}

// round 14
// speedup vs baseline: 1.0299x; 1.0060x over previous
#include <cuda_runtime.h>

// B=16384, N=100000, D=128, F1=64, F2=32
// Algebraic collapse: the deep path is affine in the gathered embedding row, so
//   y[b] = dot(emb[x[b]], v) + Wo[F2 + x[b]] + c
//   u = W2^T @ Wo[0:32] (64),  v = W1^T @ u (128),  c = b1.u + b2.wo + bo
// prep kernel computes v/c once and fires ProgrammaticLaunchCompletion right
// after its writes; main kernel (PDL) issues all prep-independent gathers
// (4 rows/warp, MLP=4, fully coalesced 512B row loads), then
// GridDependencySynchronize before reading v/c. 512 blocks x 256 threads.
// FINAL: benches at the harness floor. Identical-binary re-runs give
// 10.72 / 11.01 / 10.75 us => remaining variation is measurement noise;
// warm kernel is <=2us of the total, cold ncu main kernel 6.9us.

__device__ float g_v[128];
__device__ float g_c;

__global__ void wdl_prep_kernel(const float* __restrict__ W1,
                                const float* __restrict__ b1,
                                const float* __restrict__ W2,
                                const float* __restrict__ b2,
                                const float* __restrict__ Wo,
                                const float* __restrict__ bo) {
    __shared__ float u[64];
    int t = threadIdx.x;  // 128 threads
    if (t < 64) {
        float s = 0.f;
        #pragma unroll
        for (int k = 0; k < 32; k++) s += W2[k * 64 + t] * Wo[k];
        u[t] = s;
    }
    __syncthreads();
    {
        float s = 0.f;
        #pragma unroll
        for (int j = 0; j < 64; j++) s += W1[j * 128 + t] * u[j];
        g_v[t] = s;
    }
    if (t < 32) {
        float cc = u[t] * b1[t] + u[t + 32] * b1[t + 32] + b2[t] * Wo[t];
        #pragma unroll
        for (int off = 16; off; off >>= 1)
            cc += __shfl_xor_sync(0xffffffff, cc, off);
        if (t == 0) g_c = cc + bo[0];
    }
    // Release the dependent (PDL) grid as soon as our writes are done,
    // instead of waiting for full kernel retirement.
    __syncthreads();
    cudaTriggerProgrammaticLaunchCompletion();
}

#define THREADS 256
#define ROWS_PER_WARP 4
#define ROWS_PER_BLOCK (ROWS_PER_WARP * (THREADS / 32))  // 32

__global__ void __launch_bounds__(THREADS) wdl_main_kernel(
    const int*   __restrict__ x,
    const float* __restrict__ emb,
    const float* __restrict__ Wo,
    float* __restrict__ out) {
    int t    = threadIdx.x;
    int lane = t & 31;
    int warp = t >> 5;
    int base = blockIdx.x * ROWS_PER_BLOCK + warp * ROWS_PER_WARP;

    // ---- prep-independent work: issue every gather before the PDL sync ----
    int idxl = 0;
    if (lane < ROWS_PER_WARP) idxl = x[base + lane];
    int i0 = __shfl_sync(0xffffffff, idxl, 0);
    int i1 = __shfl_sync(0xffffffff, idxl, 1);
    int i2 = __shfl_sync(0xffffffff, idxl, 2);
    int i3 = __shfl_sync(0xffffffff, idxl, 3);

    const float4* E = reinterpret_cast<const float4*>(emb);
    float4 a0 = E[(long)i0 * 32 + lane];
    float4 a1 = E[(long)i1 * 32 + lane];
    float4 a2 = E[(long)i2 * 32 + lane];
    float4 a3 = E[(long)i3 * 32 + lane];
    float  wol = 0.f;
    if (lane < ROWS_PER_WARP) wol = Wo[32 + idxl];

    // ---- wait for prep kernel's writes (PDL dependency) ----
    cudaGridDependencySynchronize();

    float4 b = reinterpret_cast<const float4*>(g_v)[lane];
    float  c = g_c;

    float s0 = a0.x * b.x + a0.y * b.y + a0.z * b.z + a0.w * b.w;
    float s1 = a1.x * b.x + a1.y * b.y + a1.z * b.z + a1.w * b.w;
    float s2 = a2.x * b.x + a2.y * b.y + a2.z * b.z + a2.w * b.w;
    float s3 = a3.x * b.x + a3.y * b.y + a3.z * b.z + a3.w * b.w;

    #pragma unroll
    for (int off = 16; off; off >>= 1) {
        s0 += __shfl_xor_sync(0xffffffff, s0, off);
        s1 += __shfl_xor_sync(0xffffffff, s1, off);
        s2 += __shfl_xor_sync(0xffffffff, s2, off);
        s3 += __shfl_xor_sync(0xffffffff, s3, off);
    }

    if (lane < ROWS_PER_WARP) {
        float sv = (lane < 2) ? ((lane == 0) ? s0 : s1)
                              : ((lane == 2) ? s2 : s3);
        out[base + lane] = sv + wol + c;
    }
}

extern "C" void kernel_launch(void* const* d_in, const int* in_sizes, int n_in,
                              void* d_out, int out_size) {
    const int*   x   = (const int*)d_in[0];
    const float* emb = (const float*)d_in[1];
    const float* W1  = (const float*)d_in[2];
    const float* b1  = (const float*)d_in[3];
    const float* W2  = (const float*)d_in[4];
    const float* b2  = (const float*)d_in[5];
    const float* Wo  = (const float*)d_in[6];
    const float* bo  = (const float*)d_in[7];
    float* out = (float*)d_out;

    const int B = in_sizes[0];  // 16384

    wdl_prep_kernel<<<1, 128>>>(W1, b1, W2, b2, Wo, bo);

    cudaLaunchConfig_t cfg = {};
    cfg.gridDim  = dim3(B / ROWS_PER_BLOCK);  // 512
    cfg.blockDim = dim3(THREADS);
    cfg.dynamicSmemBytes = 0;
    cfg.stream = 0;
    cudaLaunchAttribute attrs[1];
    attrs[0].id = cudaLaunchAttributeProgrammaticStreamSerialization;
    attrs[0].val.programmaticStreamSerializationAllowed = 1;
    cfg.attrs = attrs;
    cfg.numAttrs = 1;
    cudaLaunchKernelEx(&cfg, wdl_main_kernel, x, emb, Wo, (float*)d_out);
}